// round 13
// baseline (speedup 1.0000x reference)
#include <cuda_runtime.h>
#include <cuda_fp16.h>
#include <stdint.h>
#include <math.h>

#define B_DIM 8192
#define C_DIM 2048
#define F_DIM 2048
#define FW    1024           // words (fp16 pairs) per row

#define BM 64
#define BN 128
#define BK 64                // k per iteration (64 fp16 = 32 words = 128B rows)
#define NKI (F_DIM / BK)     // 32 k-iterations
#define NSTG 3
#define ROWW 32                                   // words per row (XOR swizzle)
#define STAGE_WORDS ((BM + BN) * ROWW)            // 6144 words = 24KB per stage
#define SMEM_GEMM (NSTG * STAGE_WORDS * 4)        // 72KB -> 2 CTAs/SM

// ---------------- device scratch (no allocations allowed) -------------------
// fp16, K-PAIR-PERMUTED: pair index p (k=2p,2p+1) stored at word slot
// (p>>4)*16 + (p&3)*4 + ((p>>2)&3)  => an LDS.128 at word (g*16+lq*4) yields
// pairs {g16+lq, +4, +8, +12}.
__device__ uint32_t g_A [(size_t)B_DIM * FW];   // fp16(x/var) pairs
__device__ uint32_t g_Bm[(size_t)C_DIM * FW];   // fp16(means) pairs
__device__ float g_xx[B_DIM];                   // ||x/var||^2 (exact fp32)
__device__ float g_m2[C_DIM];                   // ||means||^2

// ---------------- helpers ----------------------------------------------------
__device__ __forceinline__ uint32_t smem_u32(const void* p) {
    uint32_t a;
    asm("{ .reg .u64 t; cvta.to.shared.u64 t, %1; cvt.u32.u64 %0, t; }" : "=r"(a) : "l"(p));
    return a;
}
#define CP_ASYNC16(dst, src) \
    asm volatile("cp.async.cg.shared.global [%0], [%1], 16;" :: "r"(dst), "l"(src))
#define CP_COMMIT() asm volatile("cp.async.commit_group;" ::: "memory")
#define CP_WAIT(n)  asm volatile("cp.async.wait_group %0;" :: "n"(n) : "memory")

__device__ __forceinline__ void mma_f16(float c[4], uint32_t a0, uint32_t a1,
                                        uint32_t a2, uint32_t a3,
                                        uint32_t b0, uint32_t b1) {
    asm volatile(
        "mma.sync.aligned.m16n8k16.row.col.f32.f16.f16.f32 "
        "{%0,%1,%2,%3}, {%4,%5,%6,%7}, {%8,%9}, {%0,%1,%2,%3};"
        : "+f"(c[0]), "+f"(c[1]), "+f"(c[2]), "+f"(c[3])
        : "r"(a0), "r"(a1), "r"(a2), "r"(a3), "r"(b0), "r"(b1));
}

// ---------------------------------------------------------------------------
// Convert: scale (x only) + fp16 convert + row ||.||^2 (exact fp32) +
// K-pair-permuted store via smem (coalesced uint4 in and out).
// ---------------------------------------------------------------------------
__global__ void __launch_bounds__(256)
convert_kernel(const float* __restrict__ x, const float* __restrict__ means,
               const float* __restrict__ varp)
{
    __shared__ uint32_t sperm[FW];   // 4KB permuted row of fp16 pairs
    __shared__ float sm[8];

    const int rid = blockIdx.x;
    const int x_mode = rid < B_DIM;
    const int row = x_mode ? rid : rid - B_DIM;
    const float inv = x_mode ? (1.0f / varp[0]) : 1.0f;

    const float4* p = (const float4*)((x_mode ? x : means) + (size_t)row * F_DIM);
    float ssum = 0.f;
    #pragma unroll
    for (int t = 0; t < 2; t++) {
        const int j = threadIdx.x + (t << 8);    // float4 index 0..511
        float4 v = p[j];
        float a0 = v.x * inv, a1 = v.y * inv, a2 = v.z * inv, a3 = v.w * inv;
        ssum += a0 * a0 + a1 * a1 + a2 * a2 + a3 * a3;
        __half2 h0 = __floats2half2_rn(a0, a1);  // pair p0 = 2j
        __half2 h1 = __floats2half2_rn(a2, a3);  // pair p1 = 2j+1
        const int p0 = 2 * j, p1 = 2 * j + 1;
        sperm[((p0 >> 4) << 4) | ((p0 & 3) << 2) | ((p0 >> 2) & 3)] = *(uint32_t*)&h0;
        sperm[((p1 >> 4) << 4) | ((p1 & 3) << 2) | ((p1 >> 2) & 3)] = *(uint32_t*)&h1;
    }
    __syncthreads();

    uint32_t* dst = (x_mode ? g_A : g_Bm) + (size_t)row * FW;
    ((uint4*)dst)[threadIdx.x] = ((const uint4*)sperm)[threadIdx.x];

    int lane = threadIdx.x & 31, wid = threadIdx.x >> 5;
    #pragma unroll
    for (int o = 16; o > 0; o >>= 1) ssum += __shfl_down_sync(0xffffffffu, ssum, o);
    if (lane == 0) sm[wid] = ssum;
    __syncthreads();
    if (threadIdx.x == 0) {
        float tt = sm[0];
        #pragma unroll
        for (int w = 1; w < 8; w++) tt += sm[w];
        (x_mode ? g_xx : g_m2)[row] = tt;
    }
}

// ---------------------------------------------------------------------------
// fp16 m16n8k16 mma.sync GEMM + fused distance epilogue.
// 64x128x64 tile (2048 CTAs -> 6.92 waves, 92%-full tail), 8 warps 2x4
// (warp tile 32x32), 3-stage cp.async, 2 CTAs/SM.
// ---------------------------------------------------------------------------
__global__ void __launch_bounds__(256, 2)
gemm_kernel(float* __restrict__ expo, float* __restrict__ dist)
{
    extern __shared__ uint32_t smem[];

    const int tid  = threadIdx.x;
    const int wid  = tid >> 5;
    const int lane = tid & 31;
    const int lq   = lane & 3;
    const int lr   = lane >> 2;
    const int wm   = (wid >> 2) * 32;   // warp M offset (0,32)
    const int wn   = (wid & 3) * 32;    // warp N offset (0,32,64,96)
    const int blockM = blockIdx.y * BM;
    const int blockN = blockIdx.x * BN;

    const uint32_t sbase = smem_u32(smem);

    float acc[2][4][4];
    #pragma unroll
    for (int i = 0; i < 2; i++)
        #pragma unroll
        for (int j = 0; j < 4; j++)
            #pragma unroll
            for (int e = 0; e < 4; e++) acc[i][j][e] = 0.f;

    const uint32_t* gA = g_A  + (size_t)blockM * FW;
    const uint32_t* gB = g_Bm + (size_t)blockN * FW;

    auto load_stage = [&](int stage, int kiter) {
        const uint32_t abase = sbase + (uint32_t)(stage * STAGE_WORDS) * 4u;
        const uint32_t bbase = abase + (uint32_t)(BM * ROWW) * 4u;
        const int k0w = kiter * ROWW;             // word offset in gmem row
        #pragma unroll
        for (int t = 0; t < 2; t++) {             // A: 512 16B-chunks
            int id = tid + (t << 8);
            int m = id >> 3, c = id & 7;
            uint32_t w = (uint32_t)((c * 4) ^ ((m & 1) << 4));
            CP_ASYNC16(abase + (uint32_t)(m * ROWW + w) * 4u,
                       (const char*)(gA + (size_t)m * FW + k0w + c * 4));
        }
        #pragma unroll
        for (int t = 0; t < 4; t++) {             // B: 1024 16B-chunks
            int id = tid + (t << 8);
            int m = id >> 3, c = id & 7;
            uint32_t w = (uint32_t)((c * 4) ^ ((m & 1) << 4));
            CP_ASYNC16(bbase + (uint32_t)(m * ROWW + w) * 4u,
                       (const char*)(gB + (size_t)m * FW + k0w + c * 4));
        }
    };

    load_stage(0, 0); CP_COMMIT();
    load_stage(1, 1); CP_COMMIT();

    int stage = 0, nstage = 2;
    for (int i = 0; i < NKI; i++) {
        CP_WAIT(NSTG - 2);
        __syncthreads();

        // next-stage loads issued first so LSU overlaps the MMA block
        const int nxt = i + NSTG - 1;
        if (nxt < NKI) load_stage(nstage, nxt);
        CP_COMMIT();

        const uint32_t* A  = smem + stage * STAGE_WORDS;
        const uint32_t* Bf = A + BM * ROWW;

        #pragma unroll
        for (int g = 0; g < 2; g++) {             // 16-word k-group (32 k)
            const int wbase = g * 16 + lq * 4;
            uint4 a4l[2], a4h[2], b4[4];
            #pragma unroll
            for (int mt = 0; mt < 2; mt++) {
                const int r0 = wm + mt * 16 + lr;
                const int r1 = r0 + 8;
                a4l[mt] = *(const uint4*)(A + r0 * ROWW + (wbase ^ ((r0 & 1) << 4)));
                a4h[mt] = *(const uint4*)(A + r1 * ROWW + (wbase ^ ((r1 & 1) << 4)));
            }
            #pragma unroll
            for (int nt = 0; nt < 4; nt++) {
                const int n0 = wn + nt * 8 + lr;
                b4[nt] = *(const uint4*)(Bf + n0 * ROWW + (wbase ^ ((n0 & 1) << 4)));
            }
            #pragma unroll
            for (int mt = 0; mt < 2; mt++)
                #pragma unroll
                for (int nt = 0; nt < 4; nt++)
                    mma_f16(acc[mt][nt], a4l[mt].x, a4h[mt].x, a4l[mt].y, a4h[mt].y,
                            b4[nt].x, b4[nt].y);
            #pragma unroll
            for (int mt = 0; mt < 2; mt++)
                #pragma unroll
                for (int nt = 0; nt < 4; nt++)
                    mma_f16(acc[mt][nt], a4l[mt].z, a4h[mt].z, a4l[mt].w, a4h[mt].w,
                            b4[nt].z, b4[nt].w);
        }

        stage  = (stage  == NSTG - 1) ? 0 : stage + 1;
        nstage = (nstage == NSTG - 1) ? 0 : nstage + 1;
    }

    // -------- epilogue: d = sqrt(max(xx + m2 - 2*cross, 0)) --------
    #pragma unroll
    for (int mt = 0; mt < 2; mt++) {
        const int r0 = blockM + wm + mt * 16 + lr;
        const int r1 = r0 + 8;
        const float xx0 = __ldg(&g_xx[r0]);
        const float xx1 = __ldg(&g_xx[r1]);
        #pragma unroll
        for (int nt = 0; nt < 4; nt++) {
            const int c0 = blockN + wn + nt * 8 + 2 * lq;
            const float2 m2 = *(const float2*)(g_m2 + c0);
            float d00 = sqrtf(fmaxf(fmaf(-2.f, acc[mt][nt][0], xx0 + m2.x), 0.f));
            float d01 = sqrtf(fmaxf(fmaf(-2.f, acc[mt][nt][1], xx0 + m2.y), 0.f));
            float d10 = sqrtf(fmaxf(fmaf(-2.f, acc[mt][nt][2], xx1 + m2.x), 0.f));
            float d11 = sqrtf(fmaxf(fmaf(-2.f, acc[mt][nt][3], xx1 + m2.y), 0.f));
            *(float2*)(dist + (size_t)r0 * C_DIM + c0) = make_float2(d00, d01);
            *(float2*)(dist + (size_t)r1 * C_DIM + c0) = make_float2(d10, d11);
            *(float2*)(expo + (size_t)r0 * C_DIM + c0) = make_float2(-d00, -d01);
            *(float2*)(expo + (size_t)r1 * C_DIM + c0) = make_float2(-d10, -d11);
        }
    }
}

// ---------------------------------------------------------------------------
// Row softmax over C=2048: one block per row (memory-floor bound).
// ---------------------------------------------------------------------------
__global__ void __launch_bounds__(256)
softmax_kernel(const float* __restrict__ expo, float* __restrict__ probs)
{
    __shared__ float sm[32];
    const int row = blockIdx.x;
    const int t = threadIdx.x;
    const float4* e = (const float4*)(expo + (size_t)row * C_DIM);
    float4* p = (float4*)(probs + (size_t)row * C_DIM);

    float4 v0 = e[t];
    float4 v1 = e[t + 256];

    float mx = fmaxf(fmaxf(fmaxf(v0.x, v0.y), fmaxf(v0.z, v0.w)),
                     fmaxf(fmaxf(v1.x, v1.y), fmaxf(v1.z, v1.w)));
    int lane = t & 31, wid = t >> 5;
    #pragma unroll
    for (int o = 16; o > 0; o >>= 1) mx = fmaxf(mx, __shfl_down_sync(0xffffffffu, mx, o));
    if (lane == 0) sm[wid] = mx;
    __syncthreads();
    if (t == 0) {
        float m = sm[0];
        #pragma unroll
        for (int w = 1; w < 8; w++) m = fmaxf(m, sm[w]);
        sm[0] = m;
    }
    __syncthreads();
    mx = sm[0];
    __syncthreads();

    float4 x0, x1;
    x0.x = __expf(v0.x - mx); x0.y = __expf(v0.y - mx);
    x0.z = __expf(v0.z - mx); x0.w = __expf(v0.w - mx);
    x1.x = __expf(v1.x - mx); x1.y = __expf(v1.y - mx);
    x1.z = __expf(v1.z - mx); x1.w = __expf(v1.w - mx);
    float s = x0.x + x0.y + x0.z + x0.w + x1.x + x1.y + x1.z + x1.w;
    #pragma unroll
    for (int o = 16; o > 0; o >>= 1) s += __shfl_down_sync(0xffffffffu, s, o);
    if (lane == 0) sm[wid] = s;
    __syncthreads();
    if (t == 0) {
        float acc = sm[0];
        #pragma unroll
        for (int w = 1; w < 8; w++) acc += sm[w];
        sm[0] = acc;
    }
    __syncthreads();
    const float rinv = 1.0f / sm[0];

    x0.x *= rinv; x0.y *= rinv; x0.z *= rinv; x0.w *= rinv;
    x1.x *= rinv; x1.y *= rinv; x1.z *= rinv; x1.w *= rinv;
    p[t] = x0;
    p[t + 256] = x1;
}

// ---------------------------------------------------------------------------
extern "C" void kernel_launch(void* const* d_in, const int* in_sizes, int n_in,
                              void* d_out, int out_size)
{
    const float* x     = (const float*)d_in[0];
    const float* means = (const float*)d_in[1];
    const float* var   = (const float*)d_in[2];

    float* probs = (float*)d_out;
    float* expo  = probs + (size_t)B_DIM * C_DIM;
    float* dist  = expo  + (size_t)B_DIM * C_DIM;

    cudaFuncSetAttribute(gemm_kernel, cudaFuncAttributeMaxDynamicSharedMemorySize, SMEM_GEMM);

    convert_kernel<<<B_DIM + C_DIM, 256>>>(x, means, var);
    gemm_kernel<<<dim3(C_DIM / BN, B_DIM / BM), 256, SMEM_GEMM>>>(expo, dist);
    softmax_kernel<<<B_DIM, 256>>>(expo, probs);
}

// round 14
// speedup vs baseline: 1.1542x; 1.1542x over previous
#include <cuda_runtime.h>
#include <cuda_fp16.h>
#include <stdint.h>
#include <math.h>

#define B_DIM 8192
#define C_DIM 2048
#define F_DIM 2048
#define FW    1024           // words (fp16 pairs) per row

#define BM 128
#define BN 128
#define BK 64                // k per iteration (64 fp16 = 32 words = 128B rows)
#define NKI (F_DIM / BK)     // 32 k-iterations
#define NSTG 3
#define ROWW 32                                   // words per row (XOR swizzle)
#define STAGE_WORDS (2 * 128 * ROWW)              // A + B per stage = 8192 words (32KB)
#define SMEM_GEMM (NSTG * STAGE_WORDS * 4)        // 96KB -> 2 CTAs/SM

// ---------------- device scratch (no allocations allowed) -------------------
// fp16, K-PAIR-PERMUTED: pair index p (k=2p,2p+1) stored at word slot
// (p>>4)*16 + (p&3)*4 + ((p>>2)&3)  => an LDS.128 at word (g*16+lq*4) yields
// pairs {g16+lq, +4, +8, +12}.
__device__ uint32_t g_A [(size_t)B_DIM * FW];   // fp16(x/var) pairs
__device__ uint32_t g_Bm[(size_t)C_DIM * FW];   // fp16(means) pairs
__device__ float g_xx[B_DIM];                   // ||x/var||^2 (exact fp32)
__device__ float g_m2[C_DIM];                   // ||means||^2

// ---------------- helpers ----------------------------------------------------
__device__ __forceinline__ uint32_t smem_u32(const void* p) {
    uint32_t a;
    asm("{ .reg .u64 t; cvta.to.shared.u64 t, %1; cvt.u32.u64 %0, t; }" : "=r"(a) : "l"(p));
    return a;
}
#define CP_ASYNC16(dst, src) \
    asm volatile("cp.async.cg.shared.global [%0], [%1], 16;" :: "r"(dst), "l"(src))
#define CP_COMMIT() asm volatile("cp.async.commit_group;" ::: "memory")
#define CP_WAIT(n)  asm volatile("cp.async.wait_group %0;" :: "n"(n) : "memory")

__device__ __forceinline__ void mma_f16(float c[4], uint32_t a0, uint32_t a1,
                                        uint32_t a2, uint32_t a3,
                                        uint32_t b0, uint32_t b1) {
    asm volatile(
        "mma.sync.aligned.m16n8k16.row.col.f32.f16.f16.f32 "
        "{%0,%1,%2,%3}, {%4,%5,%6,%7}, {%8,%9}, {%0,%1,%2,%3};"
        : "+f"(c[0]), "+f"(c[1]), "+f"(c[2]), "+f"(c[3])
        : "r"(a0), "r"(a1), "r"(a2), "r"(a3), "r"(b0), "r"(b1));
}

// ---------------------------------------------------------------------------
// Convert: scale (x only) + fp16 convert + row ||.||^2 (exact fp32) +
// K-pair-permuted store via smem (coalesced uint4 in and out).
// Fused: rid < B_DIM -> x rows, else means rows.
// ---------------------------------------------------------------------------
__global__ void __launch_bounds__(256)
convert_kernel(const float* __restrict__ x, const float* __restrict__ means,
               const float* __restrict__ varp)
{
    __shared__ uint32_t sperm[FW];   // 4KB permuted row of fp16 pairs
    __shared__ float sm[8];

    const int rid = blockIdx.x;
    const int x_mode = rid < B_DIM;
    const int row = x_mode ? rid : rid - B_DIM;
    const float inv = x_mode ? (1.0f / varp[0]) : 1.0f;

    const float4* p = (const float4*)((x_mode ? x : means) + (size_t)row * F_DIM);
    float ssum = 0.f;
    #pragma unroll
    for (int t = 0; t < 2; t++) {
        const int j = threadIdx.x + (t << 8);    // float4 index 0..511
        float4 v = p[j];
        float a0 = v.x * inv, a1 = v.y * inv, a2 = v.z * inv, a3 = v.w * inv;
        ssum += a0 * a0 + a1 * a1 + a2 * a2 + a3 * a3;
        __half2 h0 = __floats2half2_rn(a0, a1);  // pair p0 = 2j
        __half2 h1 = __floats2half2_rn(a2, a3);  // pair p1 = 2j+1
        const int p0 = 2 * j, p1 = 2 * j + 1;
        sperm[((p0 >> 4) << 4) | ((p0 & 3) << 2) | ((p0 >> 2) & 3)] = *(uint32_t*)&h0;
        sperm[((p1 >> 4) << 4) | ((p1 & 3) << 2) | ((p1 >> 2) & 3)] = *(uint32_t*)&h1;
    }
    __syncthreads();

    uint32_t* dst = (x_mode ? g_A : g_Bm) + (size_t)row * FW;
    ((uint4*)dst)[threadIdx.x] = ((const uint4*)sperm)[threadIdx.x];   // 256x16B = 4KB

    int lane = threadIdx.x & 31, wid = threadIdx.x >> 5;
    #pragma unroll
    for (int o = 16; o > 0; o >>= 1) ssum += __shfl_down_sync(0xffffffffu, ssum, o);
    if (lane == 0) sm[wid] = ssum;
    __syncthreads();
    if (threadIdx.x == 0) {
        float tt = sm[0];
        #pragma unroll
        for (int w = 1; w < 8; w++) tt += sm[w];
        (x_mode ? g_xx : g_m2)[row] = tt;
    }
}

// ---------------------------------------------------------------------------
// fp16 m16n8k16 mma.sync GEMM + fused distance epilogue.
// 128x128x64 tile, 8 warps 2x4 (warp tile 64x32), 3-stage cp.async, 2 CTAs/SM.
// (R10 measured-optimum configuration: 97% of the HMMA issue floor.)
// ---------------------------------------------------------------------------
__global__ void __launch_bounds__(256, 2)
gemm_kernel(float* __restrict__ expo, float* __restrict__ dist)
{
    extern __shared__ uint32_t smem[];

    const int tid  = threadIdx.x;
    const int wid  = tid >> 5;
    const int lane = tid & 31;
    const int lq   = lane & 3;
    const int lr   = lane >> 2;
    const int wm   = (wid >> 2) * 64;   // warp M offset (0,64)
    const int wn   = (wid & 3) * 32;    // warp N offset (0,32,64,96)
    const int blockM = blockIdx.y * BM;
    const int blockN = blockIdx.x * BN;

    const uint32_t sbase = smem_u32(smem);

    float acc[4][4][4];
    #pragma unroll
    for (int i = 0; i < 4; i++)
        #pragma unroll
        for (int j = 0; j < 4; j++)
            #pragma unroll
            for (int e = 0; e < 4; e++) acc[i][j][e] = 0.f;

    const uint32_t* gA = g_A  + (size_t)blockM * FW;
    const uint32_t* gB = g_Bm + (size_t)blockN * FW;

    auto load_stage = [&](int stage, int kiter) {
        const uint32_t abase = sbase + (uint32_t)(stage * STAGE_WORDS) * 4u;
        const uint32_t bbase = abase + 128u * ROWW * 4u;
        const int k0w = kiter * ROWW;             // word offset in gmem row
        #pragma unroll
        for (int t = 0; t < 4; t++) {             // A: 1024 16B-chunks
            int id = tid + (t << 8);
            int m = id >> 3, c = id & 7;
            uint32_t w = (uint32_t)((c * 4) ^ ((m & 1) << 4));
            CP_ASYNC16(abase + (uint32_t)(m * ROWW + w) * 4u,
                       (const char*)(gA + (size_t)m * FW + k0w + c * 4));
        }
        #pragma unroll
        for (int t = 0; t < 4; t++) {             // B: 1024 16B-chunks
            int id = tid + (t << 8);
            int m = id >> 3, c = id & 7;
            uint32_t w = (uint32_t)((c * 4) ^ ((m & 1) << 4));
            CP_ASYNC16(bbase + (uint32_t)(m * ROWW + w) * 4u,
                       (const char*)(gB + (size_t)m * FW + k0w + c * 4));
        }
    };

    load_stage(0, 0); CP_COMMIT();
    load_stage(1, 1); CP_COMMIT();

    int stage = 0, nstage = 2;
    for (int i = 0; i < NKI; i++) {
        CP_WAIT(NSTG - 2);
        __syncthreads();

        // next-stage loads issued first so LSU overlaps the MMA block
        const int nxt = i + NSTG - 1;
        if (nxt < NKI) load_stage(nstage, nxt);
        CP_COMMIT();

        const uint32_t* A  = smem + stage * STAGE_WORDS;
        const uint32_t* Bf = A + 128 * ROWW;

        #pragma unroll
        for (int g = 0; g < 2; g++) {             // 16-word k-group (32 k)
            const int wbase = g * 16 + lq * 4;
            uint4 a4l[4], a4h[4], b4[4];
            #pragma unroll
            for (int mt = 0; mt < 4; mt++) {
                const int r0 = wm + mt * 16 + lr;
                const int r1 = r0 + 8;
                a4l[mt] = *(const uint4*)(A + r0 * ROWW + (wbase ^ ((r0 & 1) << 4)));
                a4h[mt] = *(const uint4*)(A + r1 * ROWW + (wbase ^ ((r1 & 1) << 4)));
            }
            #pragma unroll
            for (int nt = 0; nt < 4; nt++) {
                const int n0 = wn + nt * 8 + lr;
                b4[nt] = *(const uint4*)(Bf + n0 * ROWW + (wbase ^ ((n0 & 1) << 4)));
            }
            #pragma unroll
            for (int mt = 0; mt < 4; mt++)
                #pragma unroll
                for (int nt = 0; nt < 4; nt++)
                    mma_f16(acc[mt][nt], a4l[mt].x, a4h[mt].x, a4l[mt].y, a4h[mt].y,
                            b4[nt].x, b4[nt].y);
            #pragma unroll
            for (int mt = 0; mt < 4; mt++)
                #pragma unroll
                for (int nt = 0; nt < 4; nt++)
                    mma_f16(acc[mt][nt], a4l[mt].z, a4h[mt].z, a4l[mt].w, a4h[mt].w,
                            b4[nt].z, b4[nt].w);
        }

        stage  = (stage  == NSTG - 1) ? 0 : stage + 1;
        nstage = (nstage == NSTG - 1) ? 0 : nstage + 1;
    }

    // -------- epilogue: d = sqrt(max(xx + m2 - 2*cross, 0)) --------
    #pragma unroll
    for (int mt = 0; mt < 4; mt++) {
        const int r0 = blockM + wm + mt * 16 + lr;
        const int r1 = r0 + 8;
        const float xx0 = g_xx[r0];
        const float xx1 = g_xx[r1];
        #pragma unroll
        for (int nt = 0; nt < 4; nt++) {
            const int c0 = blockN + wn + nt * 8 + 2 * lq;
            const float2 m2 = *(const float2*)(g_m2 + c0);
            float d00 = sqrtf(fmaxf(fmaf(-2.f, acc[mt][nt][0], xx0 + m2.x), 0.f));
            float d01 = sqrtf(fmaxf(fmaf(-2.f, acc[mt][nt][1], xx0 + m2.y), 0.f));
            float d10 = sqrtf(fmaxf(fmaf(-2.f, acc[mt][nt][2], xx1 + m2.x), 0.f));
            float d11 = sqrtf(fmaxf(fmaf(-2.f, acc[mt][nt][3], xx1 + m2.y), 0.f));
            *(float2*)(dist + (size_t)r0 * C_DIM + c0) = make_float2(d00, d01);
            *(float2*)(dist + (size_t)r1 * C_DIM + c0) = make_float2(d10, d11);
            *(float2*)(expo + (size_t)r0 * C_DIM + c0) = make_float2(-d00, -d01);
            *(float2*)(expo + (size_t)r1 * C_DIM + c0) = make_float2(-d10, -d11);
        }
    }
}

// ---------------------------------------------------------------------------
// Row softmax over C=2048: one block per row (memory-floor bound).
// ---------------------------------------------------------------------------
__global__ void __launch_bounds__(256)
softmax_kernel(const float* __restrict__ expo, float* __restrict__ probs)
{
    __shared__ float sm[32];
    const int row = blockIdx.x;
    const int t = threadIdx.x;
    const float4* e = (const float4*)(expo + (size_t)row * C_DIM);
    float4* p = (float4*)(probs + (size_t)row * C_DIM);

    float4 v0 = e[t];
    float4 v1 = e[t + 256];

    float mx = fmaxf(fmaxf(fmaxf(v0.x, v0.y), fmaxf(v0.z, v0.w)),
                     fmaxf(fmaxf(v1.x, v1.y), fmaxf(v1.z, v1.w)));
    int lane = t & 31, wid = t >> 5;
    #pragma unroll
    for (int o = 16; o > 0; o >>= 1) mx = fmaxf(mx, __shfl_down_sync(0xffffffffu, mx, o));
    if (lane == 0) sm[wid] = mx;
    __syncthreads();
    if (t == 0) {
        float m = sm[0];
        #pragma unroll
        for (int w = 1; w < 8; w++) m = fmaxf(m, sm[w]);
        sm[0] = m;
    }
    __syncthreads();
    mx = sm[0];
    __syncthreads();

    float4 x0, x1;
    x0.x = expf(v0.x - mx); x0.y = expf(v0.y - mx);
    x0.z = expf(v0.z - mx); x0.w = expf(v0.w - mx);
    x1.x = expf(v1.x - mx); x1.y = expf(v1.y - mx);
    x1.z = expf(v1.z - mx); x1.w = expf(v1.w - mx);
    float s = x0.x + x0.y + x0.z + x0.w + x1.x + x1.y + x1.z + x1.w;
    #pragma unroll
    for (int o = 16; o > 0; o >>= 1) s += __shfl_down_sync(0xffffffffu, s, o);
    if (lane == 0) sm[wid] = s;
    __syncthreads();
    if (t == 0) {
        float acc = sm[0];
        #pragma unroll
        for (int w = 1; w < 8; w++) acc += sm[w];
        sm[0] = acc;
    }
    __syncthreads();
    const float rinv = 1.0f / sm[0];

    x0.x *= rinv; x0.y *= rinv; x0.z *= rinv; x0.w *= rinv;
    x1.x *= rinv; x1.y *= rinv; x1.z *= rinv; x1.w *= rinv;
    p[t] = x0;
    p[t + 256] = x1;
}

// ---------------------------------------------------------------------------
extern "C" void kernel_launch(void* const* d_in, const int* in_sizes, int n_in,
                              void* d_out, int out_size)
{
    const float* x     = (const float*)d_in[0];
    const float* means = (const float*)d_in[1];
    const float* var   = (const float*)d_in[2];

    float* probs = (float*)d_out;
    float* expo  = probs + (size_t)B_DIM * C_DIM;
    float* dist  = expo  + (size_t)B_DIM * C_DIM;

    cudaFuncSetAttribute(gemm_kernel, cudaFuncAttributeMaxDynamicSharedMemorySize, SMEM_GEMM);

    convert_kernel<<<B_DIM + C_DIM, 256>>>(x, means, var);
    gemm_kernel<<<dim3(C_DIM / BN, B_DIM / BM), 256, SMEM_GEMM>>>(expo, dist);
    softmax_kernel<<<B_DIM, 256>>>(expo, probs);
}

// round 15
// speedup vs baseline: 1.1543x; 1.0001x over previous
#include <cuda_runtime.h>
#include <cuda_fp16.h>
#include <stdint.h>
#include <math.h>

#define B_DIM 8192
#define C_DIM 2048
#define F_DIM 2048
#define FW    1024           // words (fp16 pairs) per row

#define BM 128
#define BN 128
#define BK 64                // k per iteration (64 fp16 = 32 words = 128B rows)
#define NKI (F_DIM / BK)     // 32 k-iterations
#define NSTG 3
#define ROWW 32                                   // words per row (XOR swizzle)
#define STAGE_WORDS (2 * 128 * ROWW)              // A + B per stage = 8192 words (32KB)
#define SMEM_GEMM (NSTG * STAGE_WORDS * 4)        // 96KB -> 2 CTAs/SM

// ---------------- device scratch (no allocations allowed) -------------------
// fp16, K-PAIR-PERMUTED: pair index p (k=2p,2p+1) stored at word slot
// (p>>4)*16 + (p&3)*4 + ((p>>2)&3)  => an LDS.128 at word (g*16+lq*4) yields
// pairs {g16+lq, +4, +8, +12}.
__device__ uint32_t g_A [(size_t)B_DIM * FW];   // fp16(x/var) pairs
__device__ uint32_t g_Bm[(size_t)C_DIM * FW];   // fp16(means) pairs
__device__ float g_xx[B_DIM];                   // ||x/var||^2 (exact fp32)
__device__ float g_m2[C_DIM];                   // ||means||^2

// ---------------- helpers ----------------------------------------------------
__device__ __forceinline__ uint32_t smem_u32(const void* p) {
    uint32_t a;
    asm("{ .reg .u64 t; cvta.to.shared.u64 t, %1; cvt.u32.u64 %0, t; }" : "=r"(a) : "l"(p));
    return a;
}
#define CP_ASYNC16(dst, src) \
    asm volatile("cp.async.cg.shared.global [%0], [%1], 16;" :: "r"(dst), "l"(src))
#define CP_COMMIT() asm volatile("cp.async.commit_group;" ::: "memory")
#define CP_WAIT(n)  asm volatile("cp.async.wait_group %0;" :: "n"(n) : "memory")

__device__ __forceinline__ void mma_f16(float c[4], uint32_t a0, uint32_t a1,
                                        uint32_t a2, uint32_t a3,
                                        uint32_t b0, uint32_t b1) {
    asm volatile(
        "mma.sync.aligned.m16n8k16.row.col.f32.f16.f16.f32 "
        "{%0,%1,%2,%3}, {%4,%5,%6,%7}, {%8,%9}, {%0,%1,%2,%3};"
        : "+f"(c[0]), "+f"(c[1]), "+f"(c[2]), "+f"(c[3])
        : "r"(a0), "r"(a1), "r"(a2), "r"(a3), "r"(b0), "r"(b1));
}

// ---------------------------------------------------------------------------
// Convert: scale (x only) + fp16 convert + row ||.||^2 (exact fp32) +
// K-pair-permuted store via smem (coalesced uint4 in and out).
// Fused: rid < B_DIM -> x rows, else means rows.
// ---------------------------------------------------------------------------
__global__ void __launch_bounds__(256)
convert_kernel(const float* __restrict__ x, const float* __restrict__ means,
               const float* __restrict__ varp)
{
    __shared__ uint32_t sperm[FW];   // 4KB permuted row of fp16 pairs
    __shared__ float sm[8];

    const int rid = blockIdx.x;
    const int x_mode = rid < B_DIM;
    const int row = x_mode ? rid : rid - B_DIM;
    const float inv = x_mode ? (1.0f / varp[0]) : 1.0f;

    const float4* p = (const float4*)((x_mode ? x : means) + (size_t)row * F_DIM);
    float ssum = 0.f;
    #pragma unroll
    for (int t = 0; t < 2; t++) {
        const int j = threadIdx.x + (t << 8);    // float4 index 0..511
        float4 v = p[j];
        float a0 = v.x * inv, a1 = v.y * inv, a2 = v.z * inv, a3 = v.w * inv;
        ssum += a0 * a0 + a1 * a1 + a2 * a2 + a3 * a3;
        __half2 h0 = __floats2half2_rn(a0, a1);  // pair p0 = 2j
        __half2 h1 = __floats2half2_rn(a2, a3);  // pair p1 = 2j+1
        const int p0 = 2 * j, p1 = 2 * j + 1;
        sperm[((p0 >> 4) << 4) | ((p0 & 3) << 2) | ((p0 >> 2) & 3)] = *(uint32_t*)&h0;
        sperm[((p1 >> 4) << 4) | ((p1 & 3) << 2) | ((p1 >> 2) & 3)] = *(uint32_t*)&h1;
    }
    __syncthreads();

    uint32_t* dst = (x_mode ? g_A : g_Bm) + (size_t)row * FW;
    ((uint4*)dst)[threadIdx.x] = ((const uint4*)sperm)[threadIdx.x];   // 256x16B = 4KB

    int lane = threadIdx.x & 31, wid = threadIdx.x >> 5;
    #pragma unroll
    for (int o = 16; o > 0; o >>= 1) ssum += __shfl_down_sync(0xffffffffu, ssum, o);
    if (lane == 0) sm[wid] = ssum;
    __syncthreads();
    if (threadIdx.x == 0) {
        float tt = sm[0];
        #pragma unroll
        for (int w = 1; w < 8; w++) tt += sm[w];
        (x_mode ? g_xx : g_m2)[row] = tt;
    }
}

// ---------------------------------------------------------------------------
// fp16 m16n8k16 mma.sync GEMM + fused distance epilogue.
// 128x128x64 tile, 8 warps 2x4 (warp tile 64x32), 3-stage cp.async, 2 CTAs/SM.
// (Measured optimum: 97% of the sm_103a legacy-HMMA issue floor.)
// ---------------------------------------------------------------------------
__global__ void __launch_bounds__(256, 2)
gemm_kernel(float* __restrict__ expo, float* __restrict__ dist)
{
    extern __shared__ uint32_t smem[];

    const int tid  = threadIdx.x;
    const int wid  = tid >> 5;
    const int lane = tid & 31;
    const int lq   = lane & 3;
    const int lr   = lane >> 2;
    const int wm   = (wid >> 2) * 64;   // warp M offset (0,64)
    const int wn   = (wid & 3) * 32;    // warp N offset (0,32,64,96)
    const int blockM = blockIdx.y * BM;
    const int blockN = blockIdx.x * BN;

    const uint32_t sbase = smem_u32(smem);

    float acc[4][4][4];
    #pragma unroll
    for (int i = 0; i < 4; i++)
        #pragma unroll
        for (int j = 0; j < 4; j++)
            #pragma unroll
            for (int e = 0; e < 4; e++) acc[i][j][e] = 0.f;

    const uint32_t* gA = g_A  + (size_t)blockM * FW;
    const uint32_t* gB = g_Bm + (size_t)blockN * FW;

    auto load_stage = [&](int stage, int kiter) {
        const uint32_t abase = sbase + (uint32_t)(stage * STAGE_WORDS) * 4u;
        const uint32_t bbase = abase + 128u * ROWW * 4u;
        const int k0w = kiter * ROWW;             // word offset in gmem row
        #pragma unroll
        for (int t = 0; t < 4; t++) {             // A: 1024 16B-chunks
            int id = tid + (t << 8);
            int m = id >> 3, c = id & 7;
            uint32_t w = (uint32_t)((c * 4) ^ ((m & 1) << 4));
            CP_ASYNC16(abase + (uint32_t)(m * ROWW + w) * 4u,
                       (const char*)(gA + (size_t)m * FW + k0w + c * 4));
        }
        #pragma unroll
        for (int t = 0; t < 4; t++) {             // B: 1024 16B-chunks
            int id = tid + (t << 8);
            int m = id >> 3, c = id & 7;
            uint32_t w = (uint32_t)((c * 4) ^ ((m & 1) << 4));
            CP_ASYNC16(bbase + (uint32_t)(m * ROWW + w) * 4u,
                       (const char*)(gB + (size_t)m * FW + k0w + c * 4));
        }
    };

    load_stage(0, 0); CP_COMMIT();
    load_stage(1, 1); CP_COMMIT();

    int stage = 0, nstage = 2;
    for (int i = 0; i < NKI; i++) {
        CP_WAIT(NSTG - 2);
        __syncthreads();

        // next-stage loads issued first so LSU overlaps the MMA block
        const int nxt = i + NSTG - 1;
        if (nxt < NKI) load_stage(nstage, nxt);
        CP_COMMIT();

        const uint32_t* A  = smem + stage * STAGE_WORDS;
        const uint32_t* Bf = A + 128 * ROWW;

        #pragma unroll
        for (int g = 0; g < 2; g++) {             // 16-word k-group (32 k)
            const int wbase = g * 16 + lq * 4;
            uint4 a4l[4], a4h[4], b4[4];
            #pragma unroll
            for (int mt = 0; mt < 4; mt++) {
                const int r0 = wm + mt * 16 + lr;
                const int r1 = r0 + 8;
                a4l[mt] = *(const uint4*)(A + r0 * ROWW + (wbase ^ ((r0 & 1) << 4)));
                a4h[mt] = *(const uint4*)(A + r1 * ROWW + (wbase ^ ((r1 & 1) << 4)));
            }
            #pragma unroll
            for (int nt = 0; nt < 4; nt++) {
                const int n0 = wn + nt * 8 + lr;
                b4[nt] = *(const uint4*)(Bf + n0 * ROWW + (wbase ^ ((n0 & 1) << 4)));
            }
            #pragma unroll
            for (int mt = 0; mt < 4; mt++)
                #pragma unroll
                for (int nt = 0; nt < 4; nt++)
                    mma_f16(acc[mt][nt], a4l[mt].x, a4h[mt].x, a4l[mt].y, a4h[mt].y,
                            b4[nt].x, b4[nt].y);
            #pragma unroll
            for (int mt = 0; mt < 4; mt++)
                #pragma unroll
                for (int nt = 0; nt < 4; nt++)
                    mma_f16(acc[mt][nt], a4l[mt].z, a4h[mt].z, a4l[mt].w, a4h[mt].w,
                            b4[nt].z, b4[nt].w);
        }

        stage  = (stage  == NSTG - 1) ? 0 : stage + 1;
        nstage = (nstage == NSTG - 1) ? 0 : nstage + 1;
    }

    // -------- epilogue: d = sqrt(max(xx + m2 - 2*cross, 0)) --------
    #pragma unroll
    for (int mt = 0; mt < 4; mt++) {
        const int r0 = blockM + wm + mt * 16 + lr;
        const int r1 = r0 + 8;
        const float xx0 = g_xx[r0];
        const float xx1 = g_xx[r1];
        #pragma unroll
        for (int nt = 0; nt < 4; nt++) {
            const int c0 = blockN + wn + nt * 8 + 2 * lq;
            const float2 m2 = *(const float2*)(g_m2 + c0);
            float d00 = sqrtf(fmaxf(fmaf(-2.f, acc[mt][nt][0], xx0 + m2.x), 0.f));
            float d01 = sqrtf(fmaxf(fmaf(-2.f, acc[mt][nt][1], xx0 + m2.y), 0.f));
            float d10 = sqrtf(fmaxf(fmaf(-2.f, acc[mt][nt][2], xx1 + m2.x), 0.f));
            float d11 = sqrtf(fmaxf(fmaf(-2.f, acc[mt][nt][3], xx1 + m2.y), 0.f));
            *(float2*)(dist + (size_t)r0 * C_DIM + c0) = make_float2(d00, d01);
            *(float2*)(dist + (size_t)r1 * C_DIM + c0) = make_float2(d10, d11);
            *(float2*)(expo + (size_t)r0 * C_DIM + c0) = make_float2(-d00, -d01);
            *(float2*)(expo + (size_t)r1 * C_DIM + c0) = make_float2(-d10, -d11);
        }
    }
}

// ---------------------------------------------------------------------------
// Row softmax over C=2048: one block per row (memory-floor bound).
// ---------------------------------------------------------------------------
__global__ void __launch_bounds__(256)
softmax_kernel(const float* __restrict__ expo, float* __restrict__ probs)
{
    __shared__ float sm[32];
    const int row = blockIdx.x;
    const int t = threadIdx.x;
    const float4* e = (const float4*)(expo + (size_t)row * C_DIM);
    float4* p = (float4*)(probs + (size_t)row * C_DIM);

    float4 v0 = e[t];
    float4 v1 = e[t + 256];

    float mx = fmaxf(fmaxf(fmaxf(v0.x, v0.y), fmaxf(v0.z, v0.w)),
                     fmaxf(fmaxf(v1.x, v1.y), fmaxf(v1.z, v1.w)));
    int lane = t & 31, wid = t >> 5;
    #pragma unroll
    for (int o = 16; o > 0; o >>= 1) mx = fmaxf(mx, __shfl_down_sync(0xffffffffu, mx, o));
    if (lane == 0) sm[wid] = mx;
    __syncthreads();
    if (t == 0) {
        float m = sm[0];
        #pragma unroll
        for (int w = 1; w < 8; w++) m = fmaxf(m, sm[w]);
        sm[0] = m;
    }
    __syncthreads();
    mx = sm[0];
    __syncthreads();

    float4 x0, x1;
    x0.x = expf(v0.x - mx); x0.y = expf(v0.y - mx);
    x0.z = expf(v0.z - mx); x0.w = expf(v0.w - mx);
    x1.x = expf(v1.x - mx); x1.y = expf(v1.y - mx);
    x1.z = expf(v1.z - mx); x1.w = expf(v1.w - mx);
    float s = x0.x + x0.y + x0.z + x0.w + x1.x + x1.y + x1.z + x1.w;
    #pragma unroll
    for (int o = 16; o > 0; o >>= 1) s += __shfl_down_sync(0xffffffffu, s, o);
    if (lane == 0) sm[wid] = s;
    __syncthreads();
    if (t == 0) {
        float acc = sm[0];
        #pragma unroll
        for (int w = 1; w < 8; w++) acc += sm[w];
        sm[0] = acc;
    }
    __syncthreads();
    const float rinv = 1.0f / sm[0];

    x0.x *= rinv; x0.y *= rinv; x0.z *= rinv; x0.w *= rinv;
    x1.x *= rinv; x1.y *= rinv; x1.z *= rinv; x1.w *= rinv;
    p[t] = x0;
    p[t + 256] = x1;
}

// ---------------------------------------------------------------------------
extern "C" void kernel_launch(void* const* d_in, const int* in_sizes, int n_in,
                              void* d_out, int out_size)
{
    const float* x     = (const float*)d_in[0];
    const float* means = (const float*)d_in[1];
    const float* var   = (const float*)d_in[2];

    float* probs = (float*)d_out;
    float* expo  = probs + (size_t)B_DIM * C_DIM;
    float* dist  = expo  + (size_t)B_DIM * C_DIM;

    cudaFuncSetAttribute(gemm_kernel, cudaFuncAttributeMaxDynamicSharedMemorySize, SMEM_GEMM);

    convert_kernel<<<B_DIM + C_DIM, 256>>>(x, means, var);
    gemm_kernel<<<dim3(C_DIM / BN, B_DIM / BM), 256, SMEM_GEMM>>>(expo, dist);
    softmax_kernel<<<B_DIM, 256>>>(expo, probs);
}

// round 16
// speedup vs baseline: 1.1698x; 1.0134x over previous
#include <cuda_runtime.h>
#include <cuda_fp16.h>
#include <stdint.h>
#include <math.h>

#define B_DIM 8192
#define C_DIM 2048
#define F_DIM 2048
#define FW    1024           // words (fp16 pairs) per row

#define BM 128
#define BN 128
#define BK 64                // k per iteration (64 fp16 = 32 words = 128B rows)
#define NKI (F_DIM / BK)     // 32 k-iterations
#define NSTG 3
#define ROWW 32                                   // words per row (XOR swizzle)
#define STAGE_WORDS (2 * 128 * ROWW)              // A + B per stage = 8192 words (32KB)
#define SMEM_GEMM (NSTG * STAGE_WORDS * 4)        // 96KB -> 2 CTAs/SM

// ---------------- device scratch (no allocations allowed) -------------------
// fp16, K-PAIR-PERMUTED: pair index p (k=2p,2p+1) stored at word slot
// (p>>4)*16 + (p&3)*4 + ((p>>2)&3)  => an LDS.128 at word (g*16+lq*4) yields
// pairs {g16+lq, +4, +8, +12}.
__device__ uint32_t g_A [(size_t)B_DIM * FW];   // fp16(x/var) pairs
__device__ uint32_t g_Bm[(size_t)C_DIM * FW];   // fp16(means) pairs
__device__ float g_xx[B_DIM];                   // ||x/var||^2 (exact fp32)
__device__ float g_m2[C_DIM];                   // ||means||^2

// ---------------- helpers ----------------------------------------------------
__device__ __forceinline__ uint32_t smem_u32(const void* p) {
    uint32_t a;
    asm("{ .reg .u64 t; cvta.to.shared.u64 t, %1; cvt.u32.u64 %0, t; }" : "=r"(a) : "l"(p));
    return a;
}
#define CP_ASYNC16(dst, src) \
    asm volatile("cp.async.cg.shared.global [%0], [%1], 16;" :: "r"(dst), "l"(src))
#define CP_COMMIT() asm volatile("cp.async.commit_group;" ::: "memory")
#define CP_WAIT(n)  asm volatile("cp.async.wait_group %0;" :: "n"(n) : "memory")

__device__ __forceinline__ void mma_f16(float c[4], uint32_t a0, uint32_t a1,
                                        uint32_t a2, uint32_t a3,
                                        uint32_t b0, uint32_t b1) {
    asm volatile(
        "mma.sync.aligned.m16n8k16.row.col.f32.f16.f16.f32 "
        "{%0,%1,%2,%3}, {%4,%5,%6,%7}, {%8,%9}, {%0,%1,%2,%3};"
        : "+f"(c[0]), "+f"(c[1]), "+f"(c[2]), "+f"(c[3])
        : "r"(a0), "r"(a1), "r"(a2), "r"(a3), "r"(b0), "r"(b1));
}

// ---------------------------------------------------------------------------
// Convert, TWO rows per block: scale (x only) + fp16 convert + exact ||.||^2 +
// K-pair-permuted store via smem. 4 independent float4 streams per thread.
// Rows 2b, 2b+1 (same mode: B_DIM even).
// ---------------------------------------------------------------------------
__global__ void __launch_bounds__(256)
convert_kernel(const float* __restrict__ x, const float* __restrict__ means,
               const float* __restrict__ varp)
{
    __shared__ uint32_t sperm[2 * FW];   // 8KB: two permuted rows
    __shared__ float sm[16];

    const int r0 = blockIdx.x * 2;
    const int x_mode = r0 < B_DIM;
    const int row0 = x_mode ? r0 : r0 - B_DIM;
    const float inv = x_mode ? (1.0f / varp[0]) : 1.0f;
    const float* src = x_mode ? x : means;

    float ssum[2] = {0.f, 0.f};
    #pragma unroll
    for (int rr = 0; rr < 2; rr++) {
        const float4* p = (const float4*)(src + (size_t)(row0 + rr) * F_DIM);
        uint32_t* sp = sperm + rr * FW;
        #pragma unroll
        for (int t = 0; t < 2; t++) {
            const int j = threadIdx.x + (t << 8);    // float4 index 0..511
            float4 v = p[j];
            float a0 = v.x * inv, a1 = v.y * inv, a2 = v.z * inv, a3 = v.w * inv;
            ssum[rr] += a0 * a0 + a1 * a1 + a2 * a2 + a3 * a3;
            __half2 h0 = __floats2half2_rn(a0, a1);  // pair p0 = 2j
            __half2 h1 = __floats2half2_rn(a2, a3);  // pair p1 = 2j+1
            const int p0 = 2 * j, p1 = 2 * j + 1;
            sp[((p0 >> 4) << 4) | ((p0 & 3) << 2) | ((p0 >> 2) & 3)] = *(uint32_t*)&h0;
            sp[((p1 >> 4) << 4) | ((p1 & 3) << 2) | ((p1 >> 2) & 3)] = *(uint32_t*)&h1;
        }
    }
    __syncthreads();

    uint32_t* dst = (x_mode ? g_A : g_Bm) + (size_t)row0 * FW;
    ((uint4*)dst)[threadIdx.x]       = ((const uint4*)sperm)[threadIdx.x];
    ((uint4*)dst)[threadIdx.x + 256] = ((const uint4*)sperm)[threadIdx.x + 256];

    int lane = threadIdx.x & 31, wid = threadIdx.x >> 5;
    #pragma unroll
    for (int rr = 0; rr < 2; rr++) {
        float s = ssum[rr];
        #pragma unroll
        for (int o = 16; o > 0; o >>= 1) s += __shfl_down_sync(0xffffffffu, s, o);
        if (lane == 0) sm[rr * 8 + wid] = s;
    }
    __syncthreads();
    if (threadIdx.x < 2) {
        float tt = sm[threadIdx.x * 8];
        #pragma unroll
        for (int w = 1; w < 8; w++) tt += sm[threadIdx.x * 8 + w];
        (x_mode ? g_xx : g_m2)[row0 + threadIdx.x] = tt;
    }
}

// ---------------------------------------------------------------------------
// fp16 m16n8k16 mma.sync GEMM + fused distance epilogue.
// 128x128x64 tile, 8 warps 2x4 (warp tile 64x32), 3-stage cp.async, 2 CTAs/SM.
// (Measured optimum: 97% of the sm_103a legacy-HMMA issue floor. UNCHANGED.)
// ---------------------------------------------------------------------------
__global__ void __launch_bounds__(256, 2)
gemm_kernel(float* __restrict__ expo, float* __restrict__ dist)
{
    extern __shared__ uint32_t smem[];

    const int tid  = threadIdx.x;
    const int wid  = tid >> 5;
    const int lane = tid & 31;
    const int lq   = lane & 3;
    const int lr   = lane >> 2;
    const int wm   = (wid >> 2) * 64;   // warp M offset (0,64)
    const int wn   = (wid & 3) * 32;    // warp N offset (0,32,64,96)
    const int blockM = blockIdx.y * BM;
    const int blockN = blockIdx.x * BN;

    const uint32_t sbase = smem_u32(smem);

    float acc[4][4][4];
    #pragma unroll
    for (int i = 0; i < 4; i++)
        #pragma unroll
        for (int j = 0; j < 4; j++)
            #pragma unroll
            for (int e = 0; e < 4; e++) acc[i][j][e] = 0.f;

    const uint32_t* gA = g_A  + (size_t)blockM * FW;
    const uint32_t* gB = g_Bm + (size_t)blockN * FW;

    auto load_stage = [&](int stage, int kiter) {
        const uint32_t abase = sbase + (uint32_t)(stage * STAGE_WORDS) * 4u;
        const uint32_t bbase = abase + 128u * ROWW * 4u;
        const int k0w = kiter * ROWW;             // word offset in gmem row
        #pragma unroll
        for (int t = 0; t < 4; t++) {             // A: 1024 16B-chunks
            int id = tid + (t << 8);
            int m = id >> 3, c = id & 7;
            uint32_t w = (uint32_t)((c * 4) ^ ((m & 1) << 4));
            CP_ASYNC16(abase + (uint32_t)(m * ROWW + w) * 4u,
                       (const char*)(gA + (size_t)m * FW + k0w + c * 4));
        }
        #pragma unroll
        for (int t = 0; t < 4; t++) {             // B: 1024 16B-chunks
            int id = tid + (t << 8);
            int m = id >> 3, c = id & 7;
            uint32_t w = (uint32_t)((c * 4) ^ ((m & 1) << 4));
            CP_ASYNC16(bbase + (uint32_t)(m * ROWW + w) * 4u,
                       (const char*)(gB + (size_t)m * FW + k0w + c * 4));
        }
    };

    load_stage(0, 0); CP_COMMIT();
    load_stage(1, 1); CP_COMMIT();

    int stage = 0, nstage = 2;
    for (int i = 0; i < NKI; i++) {
        CP_WAIT(NSTG - 2);
        __syncthreads();

        // next-stage loads issued first so LSU overlaps the MMA block
        const int nxt = i + NSTG - 1;
        if (nxt < NKI) load_stage(nstage, nxt);
        CP_COMMIT();

        const uint32_t* A  = smem + stage * STAGE_WORDS;
        const uint32_t* Bf = A + 128 * ROWW;

        #pragma unroll
        for (int g = 0; g < 2; g++) {             // 16-word k-group (32 k)
            const int wbase = g * 16 + lq * 4;
            uint4 a4l[4], a4h[4], b4[4];
            #pragma unroll
            for (int mt = 0; mt < 4; mt++) {
                const int r0 = wm + mt * 16 + lr;
                const int r1 = r0 + 8;
                a4l[mt] = *(const uint4*)(A + r0 * ROWW + (wbase ^ ((r0 & 1) << 4)));
                a4h[mt] = *(const uint4*)(A + r1 * ROWW + (wbase ^ ((r1 & 1) << 4)));
            }
            #pragma unroll
            for (int nt = 0; nt < 4; nt++) {
                const int n0 = wn + nt * 8 + lr;
                b4[nt] = *(const uint4*)(Bf + n0 * ROWW + (wbase ^ ((n0 & 1) << 4)));
            }
            #pragma unroll
            for (int mt = 0; mt < 4; mt++)
                #pragma unroll
                for (int nt = 0; nt < 4; nt++)
                    mma_f16(acc[mt][nt], a4l[mt].x, a4h[mt].x, a4l[mt].y, a4h[mt].y,
                            b4[nt].x, b4[nt].y);
            #pragma unroll
            for (int mt = 0; mt < 4; mt++)
                #pragma unroll
                for (int nt = 0; nt < 4; nt++)
                    mma_f16(acc[mt][nt], a4l[mt].z, a4h[mt].z, a4l[mt].w, a4h[mt].w,
                            b4[nt].z, b4[nt].w);
        }

        stage  = (stage  == NSTG - 1) ? 0 : stage + 1;
        nstage = (nstage == NSTG - 1) ? 0 : nstage + 1;
    }

    // -------- epilogue: d = sqrt(max(xx + m2 - 2*cross, 0)) --------
    #pragma unroll
    for (int mt = 0; mt < 4; mt++) {
        const int r0 = blockM + wm + mt * 16 + lr;
        const int r1 = r0 + 8;
        const float xx0 = g_xx[r0];
        const float xx1 = g_xx[r1];
        #pragma unroll
        for (int nt = 0; nt < 4; nt++) {
            const int c0 = blockN + wn + nt * 8 + 2 * lq;
            const float2 m2 = *(const float2*)(g_m2 + c0);
            float d00 = sqrtf(fmaxf(fmaf(-2.f, acc[mt][nt][0], xx0 + m2.x), 0.f));
            float d01 = sqrtf(fmaxf(fmaf(-2.f, acc[mt][nt][1], xx0 + m2.y), 0.f));
            float d10 = sqrtf(fmaxf(fmaf(-2.f, acc[mt][nt][2], xx1 + m2.x), 0.f));
            float d11 = sqrtf(fmaxf(fmaf(-2.f, acc[mt][nt][3], xx1 + m2.y), 0.f));
            *(float2*)(dist + (size_t)r0 * C_DIM + c0) = make_float2(d00, d01);
            *(float2*)(dist + (size_t)r1 * C_DIM + c0) = make_float2(d10, d11);
            *(float2*)(expo + (size_t)r0 * C_DIM + c0) = make_float2(-d00, -d01);
            *(float2*)(expo + (size_t)r1 * C_DIM + c0) = make_float2(-d10, -d11);
        }
    }
}

// ---------------------------------------------------------------------------
// Row softmax, TWO rows per block: 256 threads = two 128-thread halves,
// each half owns one row (16 floats/thread). Same sync count, 2x work/block.
// ---------------------------------------------------------------------------
__global__ void __launch_bounds__(256)
softmax_kernel(const float* __restrict__ expo, float* __restrict__ probs)
{
    __shared__ float sm[2][4];
    __shared__ float sred[2];

    const int half = threadIdx.x >> 7;        // 0 or 1 -> which row
    const int t    = threadIdx.x & 127;       // 0..127 within row
    const int row  = blockIdx.x * 2 + half;
    const int lane = threadIdx.x & 31;
    const int wih  = (threadIdx.x >> 5) & 3;  // warp index within half

    const float4* e = (const float4*)(expo + (size_t)row * C_DIM);
    float4* p = (float4*)(probs + (size_t)row * C_DIM);

    float4 v[4];
    #pragma unroll
    for (int q = 0; q < 4; q++) v[q] = e[t + 128 * q];

    // --- row max ---
    float mx = -1e30f;
    #pragma unroll
    for (int q = 0; q < 4; q++)
        mx = fmaxf(mx, fmaxf(fmaxf(v[q].x, v[q].y), fmaxf(v[q].z, v[q].w)));
    #pragma unroll
    for (int o = 16; o > 0; o >>= 1) mx = fmaxf(mx, __shfl_down_sync(0xffffffffu, mx, o));
    if (lane == 0) sm[half][wih] = mx;
    __syncthreads();
    mx = fmaxf(fmaxf(sm[half][0], sm[half][1]), fmaxf(sm[half][2], sm[half][3]));

    // --- exp + row sum ---
    float s = 0.f;
    #pragma unroll
    for (int q = 0; q < 4; q++) {
        v[q].x = expf(v[q].x - mx); v[q].y = expf(v[q].y - mx);
        v[q].z = expf(v[q].z - mx); v[q].w = expf(v[q].w - mx);
        s += v[q].x + v[q].y + v[q].z + v[q].w;
    }
    #pragma unroll
    for (int o = 16; o > 0; o >>= 1) s += __shfl_down_sync(0xffffffffu, s, o);
    __syncthreads();                    // sm[][] reuse safe
    if (lane == 0) sm[half][wih] = s;
    __syncthreads();
    if ((threadIdx.x & 127) == 0)
        sred[half] = sm[half][0] + sm[half][1] + sm[half][2] + sm[half][3];
    __syncthreads();
    const float rinv = 1.0f / sred[half];

    #pragma unroll
    for (int q = 0; q < 4; q++) {
        v[q].x *= rinv; v[q].y *= rinv; v[q].z *= rinv; v[q].w *= rinv;
        p[t + 128 * q] = v[q];
    }
}

// ---------------------------------------------------------------------------
extern "C" void kernel_launch(void* const* d_in, const int* in_sizes, int n_in,
                              void* d_out, int out_size)
{
    const float* x     = (const float*)d_in[0];
    const float* means = (const float*)d_in[1];
    const float* var   = (const float*)d_in[2];

    float* probs = (float*)d_out;
    float* expo  = probs + (size_t)B_DIM * C_DIM;
    float* dist  = expo  + (size_t)B_DIM * C_DIM;

    cudaFuncSetAttribute(gemm_kernel, cudaFuncAttributeMaxDynamicSharedMemorySize, SMEM_GEMM);

    convert_kernel<<<(B_DIM + C_DIM) / 2, 256>>>(x, means, var);
    gemm_kernel<<<dim3(C_DIM / BN, B_DIM / BM), 256, SMEM_GEMM>>>(expo, dist);
    softmax_kernel<<<B_DIM / 2, 256>>>(expo, probs);
}

// round 17
// speedup vs baseline: 1.1723x; 1.0022x over previous
#include <cuda_runtime.h>
#include <cuda_fp16.h>
#include <stdint.h>
#include <math.h>

#define B_DIM 8192
#define C_DIM 2048
#define F_DIM 2048
#define FW    1024           // words (fp16 pairs) per row

#define BM 128
#define BN 128
#define BK 64                // k per iteration (64 fp16 = 32 words = 128B rows)
#define NKI (F_DIM / BK)     // 32 k-iterations
#define NSTG 3
#define ROWW 32                                   // words per row (XOR swizzle)
#define STAGE_WORDS (2 * 128 * ROWW)              // A + B per stage = 8192 words (32KB)
#define SMEM_GEMM (NSTG * STAGE_WORDS * 4)        // 96KB -> 2 CTAs/SM

// ---------------- device scratch (no allocations allowed) -------------------
// fp16, K-PAIR-PERMUTED: pair index p (k=2p,2p+1) stored at word slot
// (p>>4)*16 + (p&3)*4 + ((p>>2)&3)  => an LDS.128 at word (g*16+lq*4) yields
// pairs {g16+lq, +4, +8, +12}.
__device__ uint32_t g_A [(size_t)B_DIM * FW];   // fp16(x/var) pairs
__device__ uint32_t g_Bm[(size_t)C_DIM * FW];   // fp16(means) pairs
__device__ float g_xx[B_DIM];                   // ||x/var||^2 (exact fp32)
__device__ float g_m2[C_DIM];                   // ||means||^2

// ---------------- helpers ----------------------------------------------------
__device__ __forceinline__ uint32_t smem_u32(const void* p) {
    uint32_t a;
    asm("{ .reg .u64 t; cvta.to.shared.u64 t, %1; cvt.u32.u64 %0, t; }" : "=r"(a) : "l"(p));
    return a;
}
#define CP_ASYNC16(dst, src) \
    asm volatile("cp.async.cg.shared.global [%0], [%1], 16;" :: "r"(dst), "l"(src))
#define CP_COMMIT() asm volatile("cp.async.commit_group;" ::: "memory")
#define CP_WAIT(n)  asm volatile("cp.async.wait_group %0;" :: "n"(n) : "memory")

__device__ __forceinline__ void mma_f16(float c[4], uint32_t a0, uint32_t a1,
                                        uint32_t a2, uint32_t a3,
                                        uint32_t b0, uint32_t b1) {
    asm volatile(
        "mma.sync.aligned.m16n8k16.row.col.f32.f16.f16.f32 "
        "{%0,%1,%2,%3}, {%4,%5,%6,%7}, {%8,%9}, {%0,%1,%2,%3};"
        : "+f"(c[0]), "+f"(c[1]), "+f"(c[2]), "+f"(c[3])
        : "r"(a0), "r"(a1), "r"(a2), "r"(a3), "r"(b0), "r"(b1));
}

// ---------------------------------------------------------------------------
// Convert, FOUR rows per block: scale (x only) + fp16 convert + exact ||.||^2
// + K-pair-permuted store via smem. 8 independent float4 streams per thread.
// Rows 4b..4b+3 (mode-pure: B_DIM, C_DIM divisible by 4).
// ---------------------------------------------------------------------------
__global__ void __launch_bounds__(256)
convert_kernel(const float* __restrict__ x, const float* __restrict__ means,
               const float* __restrict__ varp)
{
    __shared__ uint32_t sperm[4 * FW];   // 16KB: four permuted rows
    __shared__ float sm[32];

    const int r0 = blockIdx.x * 4;
    const int x_mode = r0 < B_DIM;
    const int row0 = x_mode ? r0 : r0 - B_DIM;
    const float inv = x_mode ? (1.0f / varp[0]) : 1.0f;
    const float* src = x_mode ? x : means;

    float ssum[4] = {0.f, 0.f, 0.f, 0.f};
    #pragma unroll
    for (int rr = 0; rr < 4; rr++) {
        const float4* p = (const float4*)(src + (size_t)(row0 + rr) * F_DIM);
        uint32_t* sp = sperm + rr * FW;
        #pragma unroll
        for (int t = 0; t < 2; t++) {
            const int j = threadIdx.x + (t << 8);    // float4 index 0..511
            float4 v = p[j];
            float a0 = v.x * inv, a1 = v.y * inv, a2 = v.z * inv, a3 = v.w * inv;
            ssum[rr] += a0 * a0 + a1 * a1 + a2 * a2 + a3 * a3;
            __half2 h0 = __floats2half2_rn(a0, a1);  // pair p0 = 2j
            __half2 h1 = __floats2half2_rn(a2, a3);  // pair p1 = 2j+1
            const int p0 = 2 * j, p1 = 2 * j + 1;
            sp[((p0 >> 4) << 4) | ((p0 & 3) << 2) | ((p0 >> 2) & 3)] = *(uint32_t*)&h0;
            sp[((p1 >> 4) << 4) | ((p1 & 3) << 2) | ((p1 >> 2) & 3)] = *(uint32_t*)&h1;
        }
    }
    __syncthreads();

    uint32_t* dst = (x_mode ? g_A : g_Bm) + (size_t)row0 * FW;
    #pragma unroll
    for (int t = 0; t < 4; t++)
        ((uint4*)dst)[threadIdx.x + 256 * t] = ((const uint4*)sperm)[threadIdx.x + 256 * t];

    int lane = threadIdx.x & 31, wid = threadIdx.x >> 5;
    #pragma unroll
    for (int rr = 0; rr < 4; rr++) {
        float s = ssum[rr];
        #pragma unroll
        for (int o = 16; o > 0; o >>= 1) s += __shfl_down_sync(0xffffffffu, s, o);
        if (lane == 0) sm[rr * 8 + wid] = s;
    }
    __syncthreads();
    if (threadIdx.x < 4) {
        float tt = sm[threadIdx.x * 8];
        #pragma unroll
        for (int w = 1; w < 8; w++) tt += sm[threadIdx.x * 8 + w];
        (x_mode ? g_xx : g_m2)[row0 + threadIdx.x] = tt;
    }
}

// ---------------------------------------------------------------------------
// fp16 m16n8k16 mma.sync GEMM + fused distance epilogue.
// 128x128x64 tile, 8 warps 2x4 (warp tile 64x32), 3-stage cp.async, 2 CTAs/SM.
// (Measured optimum: 97% of the sm_103a legacy-HMMA issue floor. UNCHANGED.)
// ---------------------------------------------------------------------------
__global__ void __launch_bounds__(256, 2)
gemm_kernel(float* __restrict__ expo, float* __restrict__ dist)
{
    extern __shared__ uint32_t smem[];

    const int tid  = threadIdx.x;
    const int wid  = tid >> 5;
    const int lane = tid & 31;
    const int lq   = lane & 3;
    const int lr   = lane >> 2;
    const int wm   = (wid >> 2) * 64;   // warp M offset (0,64)
    const int wn   = (wid & 3) * 32;    // warp N offset (0,32,64,96)
    const int blockM = blockIdx.y * BM;
    const int blockN = blockIdx.x * BN;

    const uint32_t sbase = smem_u32(smem);

    float acc[4][4][4];
    #pragma unroll
    for (int i = 0; i < 4; i++)
        #pragma unroll
        for (int j = 0; j < 4; j++)
            #pragma unroll
            for (int e = 0; e < 4; e++) acc[i][j][e] = 0.f;

    const uint32_t* gA = g_A  + (size_t)blockM * FW;
    const uint32_t* gB = g_Bm + (size_t)blockN * FW;

    auto load_stage = [&](int stage, int kiter) {
        const uint32_t abase = sbase + (uint32_t)(stage * STAGE_WORDS) * 4u;
        const uint32_t bbase = abase + 128u * ROWW * 4u;
        const int k0w = kiter * ROWW;             // word offset in gmem row
        #pragma unroll
        for (int t = 0; t < 4; t++) {             // A: 1024 16B-chunks
            int id = tid + (t << 8);
            int m = id >> 3, c = id & 7;
            uint32_t w = (uint32_t)((c * 4) ^ ((m & 1) << 4));
            CP_ASYNC16(abase + (uint32_t)(m * ROWW + w) * 4u,
                       (const char*)(gA + (size_t)m * FW + k0w + c * 4));
        }
        #pragma unroll
        for (int t = 0; t < 4; t++) {             // B: 1024 16B-chunks
            int id = tid + (t << 8);
            int m = id >> 3, c = id & 7;
            uint32_t w = (uint32_t)((c * 4) ^ ((m & 1) << 4));
            CP_ASYNC16(bbase + (uint32_t)(m * ROWW + w) * 4u,
                       (const char*)(gB + (size_t)m * FW + k0w + c * 4));
        }
    };

    load_stage(0, 0); CP_COMMIT();
    load_stage(1, 1); CP_COMMIT();

    int stage = 0, nstage = 2;
    for (int i = 0; i < NKI; i++) {
        CP_WAIT(NSTG - 2);
        __syncthreads();

        // next-stage loads issued first so LSU overlaps the MMA block
        const int nxt = i + NSTG - 1;
        if (nxt < NKI) load_stage(nstage, nxt);
        CP_COMMIT();

        const uint32_t* A  = smem + stage * STAGE_WORDS;
        const uint32_t* Bf = A + 128 * ROWW;

        #pragma unroll
        for (int g = 0; g < 2; g++) {             // 16-word k-group (32 k)
            const int wbase = g * 16 + lq * 4;
            uint4 a4l[4], a4h[4], b4[4];
            #pragma unroll
            for (int mt = 0; mt < 4; mt++) {
                const int r0 = wm + mt * 16 + lr;
                const int r1 = r0 + 8;
                a4l[mt] = *(const uint4*)(A + r0 * ROWW + (wbase ^ ((r0 & 1) << 4)));
                a4h[mt] = *(const uint4*)(A + r1 * ROWW + (wbase ^ ((r1 & 1) << 4)));
            }
            #pragma unroll
            for (int nt = 0; nt < 4; nt++) {
                const int n0 = wn + nt * 8 + lr;
                b4[nt] = *(const uint4*)(Bf + n0 * ROWW + (wbase ^ ((n0 & 1) << 4)));
            }
            #pragma unroll
            for (int mt = 0; mt < 4; mt++)
                #pragma unroll
                for (int nt = 0; nt < 4; nt++)
                    mma_f16(acc[mt][nt], a4l[mt].x, a4h[mt].x, a4l[mt].y, a4h[mt].y,
                            b4[nt].x, b4[nt].y);
            #pragma unroll
            for (int mt = 0; mt < 4; mt++)
                #pragma unroll
                for (int nt = 0; nt < 4; nt++)
                    mma_f16(acc[mt][nt], a4l[mt].z, a4h[mt].z, a4l[mt].w, a4h[mt].w,
                            b4[nt].z, b4[nt].w);
        }

        stage  = (stage  == NSTG - 1) ? 0 : stage + 1;
        nstage = (nstage == NSTG - 1) ? 0 : nstage + 1;
    }

    // -------- epilogue: d = sqrt(max(xx + m2 - 2*cross, 0)) --------
    #pragma unroll
    for (int mt = 0; mt < 4; mt++) {
        const int r0 = blockM + wm + mt * 16 + lr;
        const int r1 = r0 + 8;
        const float xx0 = g_xx[r0];
        const float xx1 = g_xx[r1];
        #pragma unroll
        for (int nt = 0; nt < 4; nt++) {
            const int c0 = blockN + wn + nt * 8 + 2 * lq;
            const float2 m2 = *(const float2*)(g_m2 + c0);
            float d00 = sqrtf(fmaxf(fmaf(-2.f, acc[mt][nt][0], xx0 + m2.x), 0.f));
            float d01 = sqrtf(fmaxf(fmaf(-2.f, acc[mt][nt][1], xx0 + m2.y), 0.f));
            float d10 = sqrtf(fmaxf(fmaf(-2.f, acc[mt][nt][2], xx1 + m2.x), 0.f));
            float d11 = sqrtf(fmaxf(fmaf(-2.f, acc[mt][nt][3], xx1 + m2.y), 0.f));
            *(float2*)(dist + (size_t)r0 * C_DIM + c0) = make_float2(d00, d01);
            *(float2*)(dist + (size_t)r1 * C_DIM + c0) = make_float2(d10, d11);
            *(float2*)(expo + (size_t)r0 * C_DIM + c0) = make_float2(-d00, -d01);
            *(float2*)(expo + (size_t)r1 * C_DIM + c0) = make_float2(-d10, -d11);
        }
    }
}

// ---------------------------------------------------------------------------
// Row softmax, FOUR rows per block: 256 threads = four 64-thread groups,
// each group owns one row (32 floats/thread). Two sync rounds for 4 rows.
// ---------------------------------------------------------------------------
__global__ void __launch_bounds__(256)
softmax_kernel(const float* __restrict__ expo, float* __restrict__ probs)
{
    __shared__ float sm[4][2];
    __shared__ float sred[4];

    const int grp  = threadIdx.x >> 6;        // 0..3 -> which row
    const int t    = threadIdx.x & 63;        // 0..63 within row
    const int row  = blockIdx.x * 4 + grp;
    const int lane = threadIdx.x & 31;
    const int wig  = (threadIdx.x >> 5) & 1;  // warp index within group

    const float4* e = (const float4*)(expo + (size_t)row * C_DIM);
    float4* p = (float4*)(probs + (size_t)row * C_DIM);

    float4 v[8];
    #pragma unroll
    for (int q = 0; q < 8; q++) v[q] = e[t + 64 * q];

    // --- row max ---
    float mx = -1e30f;
    #pragma unroll
    for (int q = 0; q < 8; q++)
        mx = fmaxf(mx, fmaxf(fmaxf(v[q].x, v[q].y), fmaxf(v[q].z, v[q].w)));
    #pragma unroll
    for (int o = 16; o > 0; o >>= 1) mx = fmaxf(mx, __shfl_down_sync(0xffffffffu, mx, o));
    if (lane == 0) sm[grp][wig] = mx;
    __syncthreads();
    mx = fmaxf(sm[grp][0], sm[grp][1]);

    // --- exp + row sum ---
    float s = 0.f;
    #pragma unroll
    for (int q = 0; q < 8; q++) {
        v[q].x = expf(v[q].x - mx); v[q].y = expf(v[q].y - mx);
        v[q].z = expf(v[q].z - mx); v[q].w = expf(v[q].w - mx);
        s += v[q].x + v[q].y + v[q].z + v[q].w;
    }
    #pragma unroll
    for (int o = 16; o > 0; o >>= 1) s += __shfl_down_sync(0xffffffffu, s, o);
    __syncthreads();                    // safe to reuse sm[][]
    if (lane == 0) sm[grp][wig] = s;
    __syncthreads();
    if ((threadIdx.x & 63) == 0) sred[grp] = sm[grp][0] + sm[grp][1];
    __syncthreads();
    const float rinv = 1.0f / sred[grp];

    #pragma unroll
    for (int q = 0; q < 8; q++) {
        v[q].x *= rinv; v[q].y *= rinv; v[q].z *= rinv; v[q].w *= rinv;
        p[t + 64 * q] = v[q];
    }
}

// ---------------------------------------------------------------------------
extern "C" void kernel_launch(void* const* d_in, const int* in_sizes, int n_in,
                              void* d_out, int out_size)
{
    const float* x     = (const float*)d_in[0];
    const float* means = (const float*)d_in[1];
    const float* var   = (const float*)d_in[2];

    float* probs = (float*)d_out;
    float* expo  = probs + (size_t)B_DIM * C_DIM;
    float* dist  = expo  + (size_t)B_DIM * C_DIM;

    cudaFuncSetAttribute(gemm_kernel, cudaFuncAttributeMaxDynamicSharedMemorySize, SMEM_GEMM);

    convert_kernel<<<(B_DIM + C_DIM) / 4, 256>>>(x, means, var);
    gemm_kernel<<<dim3(C_DIM / BN, B_DIM / BM), 256, SMEM_GEMM>>>(expo, dist);
    softmax_kernel<<<B_DIM / 4, 256>>>(expo, probs);
}